// round 1
// baseline (speedup 1.0000x reference)
#include <cuda_runtime.h>

#define N_ROWS 32768
#define K_ANCH 32
#define D_FEAT 128

// Scratch for precomputed xw = x @ w  (both branches). Allocation-free.
__device__ float g_xw[2][N_ROWS];

// Kernel 1: xw[n] = dot(x[n,:], w[0,:]).  One warp per row, float4 lanes.
__global__ __launch_bounds__(256) void xw_kernel(const float* __restrict__ x,
                                                 const float* __restrict__ w,
                                                 int which) {
    int warp = threadIdx.x >> 5;
    int lane = threadIdx.x & 31;
    int row = blockIdx.x * 8 + warp;
    if (row >= N_ROWS) return;

    float4 xv = reinterpret_cast<const float4*>(x)[row * (D_FEAT / 4) + lane];
    float4 wv = reinterpret_cast<const float4*>(w)[lane];
    float s = xv.x * wv.x + xv.y * wv.y + xv.z * wv.z + xv.w * wv.w;
    #pragma unroll
    for (int off = 16; off > 0; off >>= 1)
        s += __shfl_xor_sync(0xFFFFFFFFu, s, off);
    if (lane == 0) g_xw[which][row] = s;
}

// Kernel 2: per-row fused gather.
//   os[n,d] = (1/K) * sum_k dmax[n,k] * x[idx[n,k], d]
//   op[n,k] = dmax[n,k] * xw[idx[n,k]] + b0
// One block of 128 threads per row n (thread = feature d).
__global__ __launch_bounds__(128) void branch_kernel(const float* __restrict__ x,
                                                     const int* __restrict__ idx,
                                                     const float* __restrict__ dmax,
                                                     const float* __restrict__ b_out,
                                                     int which,
                                                     float* __restrict__ op,
                                                     float* __restrict__ os) {
    __shared__ int   s_idx[K_ANCH];
    __shared__ float s_dm[K_ANCH];

    int n = blockIdx.x;
    int t = threadIdx.x;

    if (t < K_ANCH) {
        s_idx[t] = idx[n * K_ANCH + t];
        s_dm[t]  = dmax[n * K_ANCH + t];
    }
    __syncthreads();

    float acc = 0.0f;
    #pragma unroll
    for (int k = 0; k < K_ANCH; k++) {
        acc += s_dm[k] * __ldg(&x[(size_t)s_idx[k] * D_FEAT + t]);
    }
    os[(size_t)n * D_FEAT + t] = acc * (1.0f / (float)K_ANCH);

    if (t < K_ANCH) {
        op[(size_t)n * K_ANCH + t] = s_dm[t] * g_xw[which][s_idx[t]] + b_out[0];
    }
}

extern "C" void kernel_launch(void* const* d_in, const int* in_sizes, int n_in,
                              void* d_out, int out_size) {
    const float* x1   = (const float*)d_in[0];
    const int*   idx1 = (const int*)  d_in[1];
    const float* dm1  = (const float*)d_in[2];
    const float* x2   = (const float*)d_in[3];
    const int*   idx2 = (const int*)  d_in[4];
    const float* dm2  = (const float*)d_in[5];
    const float* w    = (const float*)d_in[6];
    const float* b    = (const float*)d_in[7];

    float* out = (float*)d_out;
    float* op1 = out;                                       // [N, K]
    float* os1 = op1 + (size_t)N_ROWS * K_ANCH;             // [N, D]
    float* op2 = os1 + (size_t)N_ROWS * D_FEAT;             // [N, K]
    float* os2 = op2 + (size_t)N_ROWS * K_ANCH;             // [N, D]

    // Precompute xw for both branches.
    xw_kernel<<<N_ROWS / 8, 256>>>(x1, w, 0);
    xw_kernel<<<N_ROWS / 8, 256>>>(x2, w, 1);

    // Fused gather + reduce per branch.
    branch_kernel<<<N_ROWS, 128>>>(x1, idx1, dm1, b, 0, op1, os1);
    branch_kernel<<<N_ROWS, 128>>>(x2, idx2, dm2, b, 1, op2, os2);
}

// round 2
// speedup vs baseline: 1.3977x; 1.3977x over previous
#include <cuda_runtime.h>

#define N_ROWS 32768
#define K_ANCH 32
#define D_FEAT 128

// Precomputed xw = x @ w for both branches (allocation-free scratch).
__device__ float g_xw[2][N_ROWS];

// xw[n] = dot(x[n,:], w[0,:]). Warp per row, float4 lanes. gridDim.y = branch.
__global__ __launch_bounds__(256) void xw_kernel(const float* __restrict__ x1,
                                                 const float* __restrict__ x2,
                                                 const float* __restrict__ w) {
    int br   = blockIdx.y;
    const float* x = br ? x2 : x1;
    int warp = threadIdx.x >> 5;
    int lane = threadIdx.x & 31;
    int row  = blockIdx.x * 8 + warp;

    float4 xv = reinterpret_cast<const float4*>(x)[row * (D_FEAT / 4) + lane];
    float4 wv = reinterpret_cast<const float4*>(w)[lane];
    float s = xv.x * wv.x + xv.y * wv.y + xv.z * wv.z + xv.w * wv.w;
    #pragma unroll
    for (int off = 16; off > 0; off >>= 1)
        s += __shfl_xor_sync(0xFFFFFFFFu, s, off);
    if (lane == 0) g_xw[br][row] = s;
}

// Fused gather for both branches. Warp per row, float4 per lane.
//   os[n, lane*4 + j] = (1/K) * sum_k dm[n,k] * x[idx[n,k], lane*4 + j]
//   op[n, lane]       = dm[n,lane] * xw[idx[n,lane]] + b0
__global__ __launch_bounds__(256) void fused_gather_kernel(
    const float* __restrict__ x1, const int* __restrict__ idx1, const float* __restrict__ dm1,
    const float* __restrict__ x2, const int* __restrict__ idx2, const float* __restrict__ dm2,
    const float* __restrict__ b_out,
    float* __restrict__ op1, float* __restrict__ os1,
    float* __restrict__ op2, float* __restrict__ os2)
{
    const int br = blockIdx.y;
    const float* __restrict__ x   = br ? x2   : x1;
    const int*   __restrict__ idx = br ? idx2 : idx1;
    const float* __restrict__ dm  = br ? dm2  : dm1;
    float*       __restrict__ op  = br ? op2  : op1;
    float*       __restrict__ os  = br ? os2  : os1;
    const float* __restrict__ xw  = g_xw[br];

    const int warp = threadIdx.x >> 5;
    const int lane = threadIdx.x & 31;
    const int n    = blockIdx.x * 8 + warp;

    // Per-warp staging: packed (byte_offset, dmax_bits) per k — one LDS.64 in the loop.
    __shared__ int2 s_kd[8][K_ANCH];

    const int   a = idx[n * K_ANCH + lane];     // coalesced 128B
    const float d = dm [n * K_ANCH + lane];     // coalesced 128B
    s_kd[warp][lane] = make_int2(a * (int)(D_FEAT * sizeof(float)), __float_as_int(d));
    __syncwarp();

    // op for this lane's k (4B gather from the 128KB xw table — mostly L1-resident).
    const float opv = d * __ldg(&xw[a]) + b_out[0];

    const char* __restrict__ xb = reinterpret_cast<const char*>(x);

    float4 acc = make_float4(0.f, 0.f, 0.f, 0.f);
    #pragma unroll 8
    for (int k = 0; k < K_ANCH; k++) {
        int2  kd = s_kd[warp][k];
        float dk = __int_as_float(kd.y);
        float4 v = __ldg(reinterpret_cast<const float4*>(xb + kd.x) + lane);
        acc.x += dk * v.x;
        acc.y += dk * v.y;
        acc.z += dk * v.z;
        acc.w += dk * v.w;
    }

    const float inv = 1.0f / (float)K_ANCH;
    acc.x *= inv; acc.y *= inv; acc.z *= inv; acc.w *= inv;

    reinterpret_cast<float4*>(os)[n * (D_FEAT / 4) + lane] = acc;   // coalesced 512B
    op[n * K_ANCH + lane] = opv;                                    // coalesced 128B
}

extern "C" void kernel_launch(void* const* d_in, const int* in_sizes, int n_in,
                              void* d_out, int out_size) {
    const float* x1   = (const float*)d_in[0];
    const int*   idx1 = (const int*)  d_in[1];
    const float* dm1  = (const float*)d_in[2];
    const float* x2   = (const float*)d_in[3];
    const int*   idx2 = (const int*)  d_in[4];
    const float* dm2  = (const float*)d_in[5];
    const float* w    = (const float*)d_in[6];
    const float* b    = (const float*)d_in[7];

    float* out = (float*)d_out;
    float* op1 = out;                                       // [N, K]
    float* os1 = op1 + (size_t)N_ROWS * K_ANCH;             // [N, D]
    float* op2 = os1 + (size_t)N_ROWS * D_FEAT;             // [N, K]
    float* os2 = op2 + (size_t)N_ROWS * K_ANCH;             // [N, D]

    dim3 xg(N_ROWS / 8, 2);
    xw_kernel<<<xg, 256>>>(x1, x2, w);

    dim3 gg(N_ROWS / 8, 2);
    fused_gather_kernel<<<gg, 256>>>(x1, idx1, dm1, x2, idx2, dm2, b,
                                     op1, os1, op2, os2);
}